// round 2
// baseline (speedup 1.0000x reference)
#include <cuda_runtime.h>
#include <cuda_bf16.h>

#define STEPS 16

// Precomputed rotation coefficients, transposed so that at inner-iteration j,
// lane L reads entry [s][j][L] (pair index p = 16*L + j) -> coalesced LDG.
// c01 = (sp*ct, cp*ct, sp*st, cp*st), c2 = (ct, st)
__device__ float4 g_ce01[STEPS][16][32];
__device__ float2 g_ce2 [STEPS][16][32];
__device__ float4 g_co01[STEPS][16][32];
__device__ float2 g_co2 [STEPS][16][32];
__device__ float2 g_om[1024];   // (cos(omega), sin(omega))

__global__ void eunn_precompute(const float* __restrict__ omega,
                                const float* __restrict__ et,
                                const float* __restrict__ ot,
                                const float* __restrict__ ep,
                                const float* __restrict__ op)
{
    int idx = blockIdx.x * blockDim.x + threadIdx.x;
    if (idx < 8192) {
        // even pairs: idx = s*512 + j*32 + L ; pair p = 16L + j  (0..511, bijective)
        int s = idx >> 9, j = (idx >> 5) & 15, L = idx & 31;
        int p = 16 * L + j;
        float st, ct, sp, cp;
        sincosf(et[s * 512 + p], &st, &ct);
        sincosf(ep[s * 512 + p], &sp, &cp);
        g_ce01[s][j][L] = make_float4(sp * ct, cp * ct, sp * st, cp * st);
        g_ce2 [s][j][L] = make_float2(ct, st);
    } else if (idx < 16384) {
        // odd pairs: q = 16L + j, valid for q < 511 (row stride of ot/op is 511!)
        int t = idx - 8192;
        int s = t >> 9, j = (t >> 5) & 15, L = t & 31;
        int q = 16 * L + j;
        if (q < 511) {
            float st, ct, sp, cp;
            sincosf(ot[s * 511 + q], &st, &ct);
            sincosf(op[s * 511 + q], &sp, &cp);
            g_co01[s][j][L] = make_float4(sp * ct, cp * ct, sp * st, cp * st);
            g_co2 [s][j][L] = make_float2(ct, st);
        } else {
            g_co01[s][j][L] = make_float4(1.f, 0.f, 0.f, 0.f);  // identity
            g_co2 [s][j][L] = make_float2(1.f, 0.f);
        }
    } else if (idx < 17408) {
        int h = idx - 16384;
        float sn, cs;
        sincosf(omega[h], &sn, &cs);
        g_om[h] = make_float2(cs, sn);
    }
}

// One warp per row. Lane L owns complex elements [32L, 32L+31] in registers.
// Even sweep: pairs (2j, 2j+1) local. Odd sweep: pairs (2j+1, 2j+2) local for
// j<15; j==15 pairs lane L's element 31 with lane L+1's element 0 via shuffles.
__global__ __launch_bounds__(256)
void eunn_main(const float* __restrict__ x, float* __restrict__ out)
{
    int w    = (blockIdx.x * 256 + threadIdx.x) >> 5;   // row
    int lane = threadIdx.x & 31;

    float xr[32], xi[32];
    const float4* in4 = (const float4*)(x + (size_t)w * 2048 + (size_t)lane * 64);
#pragma unroll
    for (int i = 0; i < 16; i++) {
        float4 v = __ldg(&in4[i]);
        xr[2*i] = v.x; xi[2*i] = v.y; xr[2*i+1] = v.z; xi[2*i+1] = v.w;
    }

    for (int s = 0; s < STEPS; s++) {
        // ---------------- even sweep ----------------
#pragma unroll
        for (int j = 0; j < 16; j++) {
            float4 c = g_ce01[s][j][lane];
            float2 d = g_ce2 [s][j][lane];
            float ar = xr[2*j],   ai = xi[2*j];
            float br = xr[2*j+1], bi = xi[2*j+1];
            xr[2*j]   = ar * c.x - ai * c.y - br * c.z + bi * c.w;
            xi[2*j]   = ar * c.y + ai * c.x - br * c.w - bi * c.z;
            xr[2*j+1] = br * d.x + ar * d.y;
            xi[2*j+1] = bi * d.x + ai * d.y;
        }
        // ---------------- odd sweep ----------------
        // neighbor's (pre-sweep) element 0, for the boundary pair
        float n0r = __shfl_down_sync(0xffffffffu, xr[0], 1);
        float n0i = __shfl_down_sync(0xffffffffu, xi[0], 1);
        float sr = 0.f, si = 0.f;
#pragma unroll
        for (int j = 0; j < 16; j++) {
            float4 c = g_co01[s][j][lane];
            float2 d = g_co2 [s][j][lane];
            float ar, ai, br, bi;
            if (j < 15) { ar = xr[2*j+1]; ai = xi[2*j+1]; br = xr[2*j+2]; bi = xi[2*j+2]; }
            else        { ar = xr[31];    ai = xi[31];    br = n0r;       bi = n0i; }
            float nar = ar * c.x - ai * c.y - br * c.z + bi * c.w;
            float nai = ar * c.y + ai * c.x - br * c.w - bi * c.z;
            float nbr = br * d.x + ar * d.y;
            float nbi = bi * d.x + ai * d.y;
            if (j < 15) {
                xr[2*j+1] = nar; xi[2*j+1] = nai;
                xr[2*j+2] = nbr; xi[2*j+2] = nbi;
            } else if (lane < 31) {      // pair q=16*31+15 doesn't exist
                xr[31] = nar; xi[31] = nai;
                sr = nbr; si = nbi;       // updated value of neighbor's element 0
            }
        }
        float rr = __shfl_up_sync(0xffffffffu, sr, 1);
        float ri = __shfl_up_sync(0xffffffffu, si, 1);
        if (lane > 0) { xr[0] = rr; xi[0] = ri; }
    }

    // ---------------- final diagonal phase ----------------
#pragma unroll
    for (int k = 0; k < 32; k++) {
        float2 om = g_om[lane * 32 + k];
        float r = xr[k] * om.x - xi[k] * om.y;
        xi[k]   = xr[k] * om.y + xi[k] * om.x;
        xr[k]   = r;
    }

    float4* o4 = (float4*)(out + (size_t)w * 2048 + (size_t)lane * 64);
#pragma unroll
    for (int i = 0; i < 16; i++)
        o4[i] = make_float4(xr[2*i], xi[2*i], xr[2*i+1], xi[2*i+1]);
}

extern "C" void kernel_launch(void* const* d_in, const int* in_sizes, int n_in,
                              void* d_out, int out_size)
{
    const float* x     = (const float*)d_in[0];
    const float* omega = (const float*)d_in[1];
    const float* et    = (const float*)d_in[2];
    const float* ot    = (const float*)d_in[3];
    const float* ep    = (const float*)d_in[4];
    const float* op    = (const float*)d_in[5];

    eunn_precompute<<<68, 256>>>(omega, et, ot, ep, op);   // 68*256 = 17408 threads

    int rows = in_sizes[0] / 2048;          // 4096
    eunn_main<<<rows / 8, 256>>>(x, (float*)d_out);  // 1 warp per row, 8 rows/block
}

// round 3
// speedup vs baseline: 1.0068x; 1.0068x over previous
#include <cuda_runtime.h>
#include <cuda_bf16.h>

#define STEPS 16

// Precomputed rotation coefficients, transposed so that at inner-iteration j,
// lane L reads entry [s][j][L] (pair index p = 16*L + j) -> coalesced LDG.
// c01 = (sp*ct, cp*ct, sp*st, cp*st), c2 = (ct, st)
__device__ float4 g_ce01[STEPS][16][32];
__device__ float2 g_ce2 [STEPS][16][32];
__device__ float4 g_co01[STEPS][16][32];
__device__ float2 g_co2 [STEPS][16][32];
__device__ float2 g_om[1024];   // (cos(omega), sin(omega))

__global__ void eunn_precompute(const float* __restrict__ omega,
                                const float* __restrict__ et,
                                const float* __restrict__ ot,
                                const float* __restrict__ ep,
                                const float* __restrict__ op)
{
    int idx = blockIdx.x * blockDim.x + threadIdx.x;
    if (idx < 8192) {
        // even pairs: idx = s*512 + j*32 + L ; pair p = 16L + j  (0..511, bijective)
        int s = idx >> 9, j = (idx >> 5) & 15, L = idx & 31;
        int p = 16 * L + j;
        float st, ct, sp, cp;
        sincosf(et[s * 512 + p], &st, &ct);
        sincosf(ep[s * 512 + p], &sp, &cp);
        g_ce01[s][j][L] = make_float4(sp * ct, cp * ct, sp * st, cp * st);
        g_ce2 [s][j][L] = make_float2(ct, st);
    } else if (idx < 16384) {
        // odd pairs: q = 16L + j, valid for q < 511 (row stride of ot/op is 511!)
        int t = idx - 8192;
        int s = t >> 9, j = (t >> 5) & 15, L = t & 31;
        int q = 16 * L + j;
        if (q < 511) {
            float st, ct, sp, cp;
            sincosf(ot[s * 511 + q], &st, &ct);
            sincosf(op[s * 511 + q], &sp, &cp);
            g_co01[s][j][L] = make_float4(sp * ct, cp * ct, sp * st, cp * st);
            g_co2 [s][j][L] = make_float2(ct, st);
        } else {
            g_co01[s][j][L] = make_float4(1.f, 0.f, 0.f, 0.f);  // identity
            g_co2 [s][j][L] = make_float2(1.f, 0.f);
        }
    } else if (idx < 17408) {
        int h = idx - 16384;
        float sn, cs;
        sincosf(omega[h], &sn, &cs);
        g_om[h] = make_float2(cs, sn);
    }
}

// One warp per row. Lane L owns complex elements [32L, 32L+31] in registers.
// Even sweep: pairs (2j, 2j+1) local. Odd sweep: pairs (2j+1, 2j+2) local for
// j<15; j==15 pairs lane L's element 31 with lane L+1's element 0 via shuffles.
__global__ __launch_bounds__(256)
void eunn_main(const float* __restrict__ x, float* __restrict__ out)
{
    int w    = (blockIdx.x * 256 + threadIdx.x) >> 5;   // row
    int lane = threadIdx.x & 31;

    float xr[32], xi[32];
    const float4* in4 = (const float4*)(x + (size_t)w * 2048 + (size_t)lane * 64);
#pragma unroll
    for (int i = 0; i < 16; i++) {
        float4 v = __ldg(&in4[i]);
        xr[2*i] = v.x; xi[2*i] = v.y; xr[2*i+1] = v.z; xi[2*i+1] = v.w;
    }

    for (int s = 0; s < STEPS; s++) {
        // ---------------- even sweep ----------------
#pragma unroll
        for (int j = 0; j < 16; j++) {
            float4 c = g_ce01[s][j][lane];
            float2 d = g_ce2 [s][j][lane];
            float ar = xr[2*j],   ai = xi[2*j];
            float br = xr[2*j+1], bi = xi[2*j+1];
            xr[2*j]   = ar * c.x - ai * c.y - br * c.z + bi * c.w;
            xi[2*j]   = ar * c.y + ai * c.x - br * c.w - bi * c.z;
            xr[2*j+1] = br * d.x + ar * d.y;
            xi[2*j+1] = bi * d.x + ai * d.y;
        }
        // ---------------- odd sweep ----------------
        // neighbor's (pre-sweep) element 0, for the boundary pair
        float n0r = __shfl_down_sync(0xffffffffu, xr[0], 1);
        float n0i = __shfl_down_sync(0xffffffffu, xi[0], 1);
        float sr = 0.f, si = 0.f;
#pragma unroll
        for (int j = 0; j < 16; j++) {
            float4 c = g_co01[s][j][lane];
            float2 d = g_co2 [s][j][lane];
            float ar, ai, br, bi;
            if (j < 15) { ar = xr[2*j+1]; ai = xi[2*j+1]; br = xr[2*j+2]; bi = xi[2*j+2]; }
            else        { ar = xr[31];    ai = xi[31];    br = n0r;       bi = n0i; }
            float nar = ar * c.x - ai * c.y - br * c.z + bi * c.w;
            float nai = ar * c.y + ai * c.x - br * c.w - bi * c.z;
            float nbr = br * d.x + ar * d.y;
            float nbi = bi * d.x + ai * d.y;
            if (j < 15) {
                xr[2*j+1] = nar; xi[2*j+1] = nai;
                xr[2*j+2] = nbr; xi[2*j+2] = nbi;
            } else if (lane < 31) {      // pair q=16*31+15 doesn't exist
                xr[31] = nar; xi[31] = nai;
                sr = nbr; si = nbi;       // updated value of neighbor's element 0
            }
        }
        float rr = __shfl_up_sync(0xffffffffu, sr, 1);
        float ri = __shfl_up_sync(0xffffffffu, si, 1);
        if (lane > 0) { xr[0] = rr; xi[0] = ri; }
    }

    // ---------------- final diagonal phase ----------------
#pragma unroll
    for (int k = 0; k < 32; k++) {
        float2 om = g_om[lane * 32 + k];
        float r = xr[k] * om.x - xi[k] * om.y;
        xi[k]   = xr[k] * om.y + xi[k] * om.x;
        xr[k]   = r;
    }

    float4* o4 = (float4*)(out + (size_t)w * 2048 + (size_t)lane * 64);
#pragma unroll
    for (int i = 0; i < 16; i++)
        o4[i] = make_float4(xr[2*i], xi[2*i], xr[2*i+1], xi[2*i+1]);
}

extern "C" void kernel_launch(void* const* d_in, const int* in_sizes, int n_in,
                              void* d_out, int out_size)
{
    const float* x     = (const float*)d_in[0];
    const float* omega = (const float*)d_in[1];
    const float* et    = (const float*)d_in[2];
    const float* ot    = (const float*)d_in[3];
    const float* ep    = (const float*)d_in[4];
    const float* op    = (const float*)d_in[5];

    eunn_precompute<<<68, 256>>>(omega, et, ot, ep, op);   // 68*256 = 17408 threads

    int rows = in_sizes[0] / 2048;          // 4096
    eunn_main<<<rows / 8, 256>>>(x, (float*)d_out);  // 1 warp per row, 8 rows/block
}

// round 4
// speedup vs baseline: 2.2660x; 2.2507x over previous
#include <cuda_runtime.h>
#include <cuda_bf16.h>

#define STEPS 16

// Rotation coefficients, layout [s][slice c][j][lane L]; pair index = 128c + 4L + j.
// c01 = (sp*ct, cp*ct, sp*st, cp*st), c2 = (ct, st)
__device__ float4 g_ce01[STEPS][4][4][32];
__device__ float2 g_ce2 [STEPS][4][4][32];
__device__ float4 g_co01[STEPS][4][4][32];
__device__ float2 g_co2 [STEPS][4][4][32];
__device__ float2 g_om[1024];   // (cos(omega), sin(omega))

__global__ void eunn_precompute(const float* __restrict__ omega,
                                const float* __restrict__ et,
                                const float* __restrict__ ot,
                                const float* __restrict__ ep,
                                const float* __restrict__ op)
{
    int idx = blockIdx.x * blockDim.x + threadIdx.x;
    if (idx < 8192) {
        // even pairs p = 0..511 ; store at [s][c][j][L] with p = 128c + 4L + j
        int s = idx >> 9, p = idx & 511;
        int c = p >> 7, rem = p & 127, L = rem >> 2, j = rem & 3;
        float st, ct, sp, cp;
        sincosf(et[s * 512 + p], &st, &ct);
        sincosf(ep[s * 512 + p], &sp, &cp);
        g_ce01[s][c][j][L] = make_float4(sp * ct, cp * ct, sp * st, cp * st);
        g_ce2 [s][c][j][L] = make_float2(ct, st);
    } else if (idx < 16384) {
        // odd pairs q = 0..511 (q=511 doesn't exist -> identity); ot/op row stride = 511
        int t = idx - 8192;
        int s = t >> 9, q = t & 511;
        int c = q >> 7, rem = q & 127, L = rem >> 2, j = rem & 3;
        if (q < 511) {
            float st, ct, sp, cp;
            sincosf(ot[s * 511 + q], &st, &ct);
            sincosf(op[s * 511 + q], &sp, &cp);
            g_co01[s][c][j][L] = make_float4(sp * ct, cp * ct, sp * st, cp * st);
            g_co2 [s][c][j][L] = make_float2(ct, st);
        } else {
            g_co01[s][c][j][L] = make_float4(1.f, 0.f, 0.f, 0.f);  // exact identity
            g_co2 [s][c][j][L] = make_float2(1.f, 0.f);
        }
    } else if (idx < 17408) {
        int h = idx - 16384;
        float sn, cs;
        sincosf(omega[h], &sn, &cs);
        g_om[h] = make_float2(cs, sn);
    }
}

// Block = 256 threads = 8 warps = 2 row-groups. Each row-group = 4 warps
// (slices c=0..3) processing the SAME 4 rows. Warp (g,c) holds, per lane,
// 8 complex elements [256c + 8L, 256c + 8L + 8) of rows row0..row0+3.
// Even pairs are lane-internal. Odd pairs: 3 lane-internal + 1 lane-boundary
// (shuffle) per lane; the slice-boundary pair goes through 256B of smem.
__global__ void __launch_bounds__(256, 2)
eunn_main(const float* __restrict__ x, float* __restrict__ out)
{
    __shared__ float edge[8][4][2];   // [target warp slot][row r][re/im]

    int lane = threadIdx.x & 31;
    int wblk = threadIdx.x >> 5;      // 0..7
    int c    = wblk & 3;              // slice
    int g    = wblk >> 2;             // row-group within block
    int row0 = blockIdx.x * 8 + g * 4;
    int ebase = c * 256 + lane * 8;   // first global element owned by this lane

    float xr[4][8], xi[4][8];
#pragma unroll
    for (int r = 0; r < 4; r++) {
        const float4* p4 = (const float4*)(x + (size_t)(row0 + r) * 2048 + ebase * 2);
#pragma unroll
        for (int i = 0; i < 4; i++) {
            float4 v = __ldg(&p4[i]);
            xr[r][2*i] = v.x; xi[r][2*i] = v.y; xr[r][2*i+1] = v.z; xi[r][2*i+1] = v.w;
        }
    }

    for (int s = 0; s < STEPS; s++) {
        // ---------------- even sweep: pairs (2j, 2j+1) lane-internal ----------------
#pragma unroll
        for (int j = 0; j < 4; j++) {
            float4 cc = g_ce01[s][c][j][lane];
            float2 dd = g_ce2 [s][c][j][lane];
#pragma unroll
            for (int r = 0; r < 4; r++) {
                float ar = xr[r][2*j],   ai = xi[r][2*j];
                float br = xr[r][2*j+1], bi = xi[r][2*j+1];
                xr[r][2*j]   = ar * cc.x - ai * cc.y - br * cc.z + bi * cc.w;
                xi[r][2*j]   = ar * cc.y + ai * cc.x - br * cc.w - bi * cc.z;
                xr[r][2*j+1] = br * dd.x + ar * dd.y;
                xi[r][2*j+1] = bi * dd.x + ai * dd.y;
            }
        }

        // publish post-even element 0 of this slice to the left-neighbor warp
        if (lane == 0) {
#pragma unroll
            for (int r = 0; r < 4; r++) {
                edge[wblk][r][0] = xr[r][0];
                edge[wblk][r][1] = xi[r][0];
            }
        }
        __syncthreads();

        // neighbor's (post-even, pre-odd) element 0 for the boundary pair
        float n0r[4], n0i[4];
#pragma unroll
        for (int r = 0; r < 4; r++) {
            n0r[r] = __shfl_down_sync(0xffffffffu, xr[r][0], 1);
            n0i[r] = __shfl_down_sync(0xffffffffu, xi[r][0], 1);
        }
        if (lane == 31 && c < 3) {
#pragma unroll
            for (int r = 0; r < 4; r++) {
                n0r[r] = edge[wblk + 1][r][0];
                n0i[r] = edge[wblk + 1][r][1];
            }
        }

        // ---------------- odd sweep ----------------
        // internal pairs j=0..2: elements (2j+1, 2j+2)
#pragma unroll
        for (int j = 0; j < 3; j++) {
            float4 cc = g_co01[s][c][j][lane];
            float2 dd = g_co2 [s][c][j][lane];
#pragma unroll
            for (int r = 0; r < 4; r++) {
                float ar = xr[r][2*j+1], ai = xi[r][2*j+1];
                float br = xr[r][2*j+2], bi = xi[r][2*j+2];
                xr[r][2*j+1] = ar * cc.x - ai * cc.y - br * cc.z + bi * cc.w;
                xi[r][2*j+1] = ar * cc.y + ai * cc.x - br * cc.w - bi * cc.z;
                xr[r][2*j+2] = br * dd.x + ar * dd.y;
                xi[r][2*j+2] = bi * dd.x + ai * dd.y;
            }
        }
        // boundary pair j=3: a = element 7 (mine), b = neighbor's element 0
        {
            float4 cc = g_co01[s][c][3][lane];
            float2 dd = g_co2 [s][c][3][lane];
            float nbr[4], nbi[4];
#pragma unroll
            for (int r = 0; r < 4; r++) {
                float ar = xr[r][7], ai = xi[r][7];
                float br = n0r[r],  bi = n0i[r];
                xr[r][7] = ar * cc.x - ai * cc.y - br * cc.z + bi * cc.w;
                xi[r][7] = ar * cc.y + ai * cc.x - br * cc.w - bi * cc.z;
                nbr[r]   = br * dd.x + ar * dd.y;
                nbi[r]   = bi * dd.x + ai * dd.y;
            }
            // route updated b: lane 31 (c<3) -> smem to right warp; others -> shfl_up
            if (lane == 31 && c < 3) {
#pragma unroll
                for (int r = 0; r < 4; r++) {
                    edge[wblk + 1][r][0] = nbr[r];
                    edge[wblk + 1][r][1] = nbi[r];
                }
            }
#pragma unroll
            for (int r = 0; r < 4; r++) {
                float ur = __shfl_up_sync(0xffffffffu, nbr[r], 1);
                float ui = __shfl_up_sync(0xffffffffu, nbi[r], 1);
                if (lane > 0) { xr[r][0] = ur; xi[r][0] = ui; }
            }
        }
        __syncthreads();
        if (lane == 0 && c > 0) {
#pragma unroll
            for (int r = 0; r < 4; r++) {
                xr[r][0] = edge[wblk][r][0];
                xi[r][0] = edge[wblk][r][1];
            }
        }
    }

    // ---------------- final diagonal phase + store ----------------
#pragma unroll
    for (int r = 0; r < 4; r++) {
        float4* o4 = (float4*)(out + (size_t)(row0 + r) * 2048 + ebase * 2);
#pragma unroll
        for (int i = 0; i < 4; i++) {
            float2 m0 = g_om[ebase + 2*i];
            float2 m1 = g_om[ebase + 2*i + 1];
            float r0 = xr[r][2*i]   * m0.x - xi[r][2*i]   * m0.y;
            float i0 = xr[r][2*i]   * m0.y + xi[r][2*i]   * m0.x;
            float r1 = xr[r][2*i+1] * m1.x - xi[r][2*i+1] * m1.y;
            float i1 = xr[r][2*i+1] * m1.y + xi[r][2*i+1] * m1.x;
            o4[i] = make_float4(r0, i0, r1, i1);
        }
    }
}

extern "C" void kernel_launch(void* const* d_in, const int* in_sizes, int n_in,
                              void* d_out, int out_size)
{
    const float* x     = (const float*)d_in[0];
    const float* omega = (const float*)d_in[1];
    const float* et    = (const float*)d_in[2];
    const float* ot    = (const float*)d_in[3];
    const float* ep    = (const float*)d_in[4];
    const float* op    = (const float*)d_in[5];

    eunn_precompute<<<68, 256>>>(omega, et, ot, ep, op);   // 17408 threads

    int rows = in_sizes[0] / 2048;                         // 4096
    eunn_main<<<rows / 8, 256>>>(x, (float*)d_out);        // 8 rows per block
}